// round 6
// baseline (speedup 1.0000x reference)
#include <cuda_runtime.h>
#include <cuda_fp16.h>
#include <stdint.h>

// Problem dims (fixed by the dataset)
#define FDIM 16384   // n_features
#define DDIM 768     // d_model
#define NB   1024    // B*S
#define MCONN 262144 // n_connections

// -------- scratch (device globals; no allocation allowed) --------
__device__ __half g_udTh[(size_t)FDIM * DDIM]; // up_decoder^T fp16: [F, D] (~25 MB)
__device__ __half g_XTh[(size_t)FDIM * NB];    // up_facts^T fp16:   [F, NB] (~33 MB)
__device__ float  g_values[MCONN];             // per-connection value (fp32)
__device__ int    g_rowstart[FDIM + 1];        // CSR offsets over sorted i
__device__ int    g_j32[MCONN];                // j indices as int32

// ---------------------------------------------------------------
// Inline int64-vs-int32 detection on the i_indices buffer (values
// < 16384 => odd int32-words of an int64 array are all zero; for
// int32 data the probed words are sorted indices ~8192 != 0).
// ---------------------------------------------------------------
__device__ __forceinline__ int detect_is64(const int* raw) {
    int q = MCONN / 4;
    int nz = 0;
#pragma unroll
    for (int k = 0; k < 8; k++) nz |= raw[2 * (q + k) + 1];
    return nz ? 0 : 1;
}

__device__ __forceinline__ int idx_at(const void* p, int is64, int m) {
    return is64 ? (int)((const long long*)p)[m] : ((const int*)p)[m];
}

// ================================================================
// K1: fused prep = transpose_ud | csr_scatter | jconv
//   blocks [0, 12288)          : up_decoder [D,F] -> g_udTh [F,D]
//   blocks [12288, 13312)      : CSR row offsets (O(M) scatter)
//   blocks [13312, 14336)      : j -> int32
// ================================================================
#define K1_UD   12288   // (FDIM/32)*(DDIM/32) = 512*24
#define K1_CSR  (K1_UD + 1024)
#define K1_TOT  (K1_CSR + 1024)

__global__ __launch_bounds__(256) void k1_prep(const float* __restrict__ up_dec,
                                               const void* __restrict__ ii,
                                               const void* __restrict__ jj) {
    int b = blockIdx.x;
    if (b < K1_UD) {
        __shared__ float tile[32][33];
        int bx = b & 511;          // F tile
        int by = b >> 9;           // D tile
        int c0 = bx * 32, r0 = by * 32;
        int tx = threadIdx.x & 31, ty = threadIdx.x >> 5;   // (32, 8)
#pragma unroll
        for (int k = 0; k < 32; k += 8)
            tile[ty + k][tx] = up_dec[(size_t)(r0 + ty + k) * FDIM + (c0 + tx)];
        __syncthreads();
#pragma unroll
        for (int k = 0; k < 32; k += 8)
            g_udTh[(size_t)(c0 + ty + k) * DDIM + (r0 + tx)] = __float2half(tile[tx][ty + k]);
    } else if (b < K1_CSR) {
        int m = (b - K1_UD) * 256 + threadIdx.x;
        int is64 = detect_is64((const int*)ii);
        int cur = idx_at(ii, is64, m);
        int prev = (m == 0) ? -1 : idx_at(ii, is64, m - 1);
        for (int i = prev + 1; i <= cur; i++) g_rowstart[i] = m;
        if (m == MCONN - 1)
            for (int i = cur + 1; i <= FDIM; i++) g_rowstart[i] = MCONN;
    } else {
        int m = (b - K1_CSR) * 256 + threadIdx.x;
        int is64 = detect_is64((const int*)ii);
        g_j32[m] = idx_at(jj, is64, m);
    }
}

// ================================================================
// K2: fused = values (blocks [0,2048)) | transpose_x (rest)
//   values: one warp per i-group, de row cached in registers,
//           fp16 gather of udT rows, fp32 accumulate.
//   transpose_x: up_facts [NB,F] -> g_XTh [F,NB] fp16.
// ================================================================
#define K2_VAL  2048    // FDIM/8 (8 warps per block)
#define K2_TOT  (K2_VAL + 16384)   // + (FDIM/32)*(NB/32) = 512*32

__global__ __launch_bounds__(256) void k2_values_xt(const float* __restrict__ de,
                                                    const float* __restrict__ up_facts) {
    int b = blockIdx.x;
    if (b < K2_VAL) {
        int warp = b * 8 + (threadIdx.x >> 5);
        int lane = threadIdx.x & 31;
        int i = warp;
        int s = g_rowstart[i];
        int e = g_rowstart[i + 1];
        if (s == e) return;

        // Cache de[i,:] lane slice: elements 8*(2*lane+64k) .. +7, k<3
        float a[3][8];
        const float4* dev = (const float4*)(de + (size_t)i * DDIM);
#pragma unroll
        for (int k = 0; k < 3; k++) {
            float4 p = dev[2 * lane + 64 * k];
            float4 q = dev[2 * lane + 64 * k + 1];
            a[k][0] = p.x; a[k][1] = p.y; a[k][2] = p.z; a[k][3] = p.w;
            a[k][4] = q.x; a[k][5] = q.y; a[k][6] = q.z; a[k][7] = q.w;
        }

        for (int m = s; m < e; m++) {
            int j = g_j32[m];
            const uint4* u = (const uint4*)(g_udTh + (size_t)j * DDIM);
            float sum = 0.f;
#pragma unroll
            for (int k = 0; k < 3; k++) {
                uint4 bb = u[lane + 32 * k];
                const __half2* h = (const __half2*)&bb;
#pragma unroll
                for (int t = 0; t < 4; t++) {
                    float2 f = __half22float2(h[t]);
                    sum += a[k][2 * t] * f.x + a[k][2 * t + 1] * f.y;
                }
            }
#pragma unroll
            for (int o = 16; o; o >>= 1) sum += __shfl_xor_sync(0xffffffffu, sum, o);
            if (lane == 0) g_values[m] = sum;
        }
    } else {
        __shared__ float tile[32][33];
        int b2 = b - K2_VAL;
        int bx = b2 & 511;          // F tile
        int by = b2 >> 9;           // NB tile
        int c0 = bx * 32, r0 = by * 32;
        int tx = threadIdx.x & 31, ty = threadIdx.x >> 5;
#pragma unroll
        for (int k = 0; k < 32; k += 8)
            tile[ty + k][tx] = up_facts[(size_t)(r0 + ty + k) * FDIM + (c0 + tx)];
        __syncthreads();
#pragma unroll
        for (int k = 0; k < 32; k += 8)
            g_XTh[(size_t)(c0 + ty + k) * NB + (r0 + tx)] = __float2half(tile[tx][ty + k]);
    }
}

// ================================================================
// K3: SpMM. out[n,i] = sum_{m in group(i)} values[m] * XT[j_m, n]
// Block: 256 threads, each thread owns 4 consecutive n (one 8B load
// per connection). Tile: ITILE=16 i-rows x all 1024 n.
// smem entries pre-packed {byte_offset = j*NB*2, value}.
// ================================================================
#define ITILE 16
#define NTHR  256
#define CHUNK 512

__global__ __launch_bounds__(NTHR) void k3_spmm(float* __restrict__ out) {
    __shared__ int2 se[CHUNK];          // {xt byte offset, value bits}
    __shared__ int  soff[ITILE + 1];

    int i0 = blockIdx.x * ITILE;
    int n0 = threadIdx.x * 4;

    if (threadIdx.x <= ITILE) soff[threadIdx.x] = g_rowstart[i0 + threadIdx.x];
    __syncthreads();

    int mbase = soff[0];
    int mend  = soff[ITILE];

    const char* xbase = (const char*)g_XTh + n0 * 2;

    float4 acc[ITILE];
#pragma unroll
    for (int k = 0; k < ITILE; k++) acc[k] = make_float4(0.f, 0.f, 0.f, 0.f);

    for (int cb = mbase; cb < mend; cb += CHUNK) {
        int cend = min(cb + CHUNK, mend);
        __syncthreads();
        for (int t = cb + threadIdx.x; t < cend; t += NTHR) {
            int2 e;
            e.x = g_j32[t] << 11;            // j * NB * sizeof(half)
            e.y = __float_as_int(g_values[t]);
            se[t - cb] = e;
        }
        __syncthreads();
#pragma unroll
        for (int il = 0; il < ITILE; il++) {
            int ms = max(soff[il], cb);
            int me = min(soff[il + 1], cend);
            for (int m = ms; m < me; m++) {
                int2 e = se[m - cb];
                float v = __int_as_float(e.y);
                uint2 u = *(const uint2*)(xbase + e.x);
                float2 f0 = __half22float2(*(const __half2*)&u.x);
                float2 f1 = __half22float2(*(const __half2*)&u.y);
                acc[il].x += v * f0.x;
                acc[il].y += v * f0.y;
                acc[il].z += v * f1.x;
                acc[il].w += v * f1.y;
            }
        }
    }

    // Write 16 contiguous i-outputs for each of this thread's 4 n rows
#pragma unroll
    for (int r = 0; r < 4; r++) {
        float4* o = (float4*)(out + (size_t)(n0 + r) * FDIM + i0);
#pragma unroll
        for (int k = 0; k < 4; k++) {
            const float* s0 = (const float*)&acc[4 * k];
            const float* s1 = (const float*)&acc[4 * k + 1];
            const float* s2 = (const float*)&acc[4 * k + 2];
            const float* s3 = (const float*)&acc[4 * k + 3];
            o[k] = make_float4(s0[r], s1[r], s2[r], s3[r]);
        }
    }
}

// ---------------------------------------------------------------
extern "C" void kernel_launch(void* const* d_in, const int* in_sizes, int n_in,
                              void* d_out, int out_size) {
    const float* up_facts = (const float*)d_in[0];   // [NB, F]
    const float* down_enc = (const float*)d_in[1];   // [F, D]
    const float* up_dec   = (const float*)d_in[2];   // [D, F]
    const void*  ii       = d_in[3];                 // [M] sorted (int32 or int64)
    const void*  jj       = d_in[4];                 // [M]
    float* out = (float*)d_out;                      // [NB, F]

    k1_prep<<<K1_TOT, 256>>>(up_dec, ii, jj);
    k2_values_xt<<<K2_TOT, 256>>>(down_enc, up_facts);
    k3_spmm<<<FDIM / ITILE, NTHR>>>(out);
}

// round 7
// speedup vs baseline: 1.2986x; 1.2986x over previous
#include <cuda_runtime.h>
#include <cuda_fp16.h>
#include <stdint.h>

// Problem dims (fixed by the dataset)
#define FDIM 16384   // n_features
#define DDIM 768     // d_model
#define NB   1024    // B*S
#define MCONN 262144 // n_connections

// -------- scratch (device globals; no allocation allowed) --------
__device__ __half g_udTh[(size_t)FDIM * DDIM]; // up_decoder^T fp16: [F, D] (~25 MB)
__device__ __half g_XTh[(size_t)FDIM * NB];    // up_facts^T fp16:   [F, NB] (~33 MB)
__device__ float  g_values[MCONN];             // per-connection value (fp32)
__device__ int    g_rowstart[FDIM + 1];        // CSR offsets over sorted i
__device__ int    g_j32[MCONN];                // j indices as int32

// ---------------------------------------------------------------
// Inline int64-vs-int32 detection on the i_indices buffer (values
// < 16384 => odd int32-words of an int64 array are all zero; for
// int32 data the probed words are sorted indices ~8192 != 0).
// ---------------------------------------------------------------
__device__ __forceinline__ int detect_is64(const int* raw) {
    int q = MCONN / 4;
    int nz = 0;
#pragma unroll
    for (int k = 0; k < 8; k++) nz |= raw[2 * (q + k) + 1];
    return nz ? 0 : 1;
}

__device__ __forceinline__ int idx_at(const void* p, int is64, int m) {
    return is64 ? (int)((const long long*)p)[m] : ((const int*)p)[m];
}

// ================================================================
// K1: fused prep = transpose_ud | csr_scatter | jconv
//   blocks [0, 12288)     : up_decoder [D,F] -> g_udTh [F,D]
//   blocks [12288, 13312) : CSR row offsets (O(M) scatter)
//   blocks [13312, 14336) : j -> int32
// ================================================================
#define K1_UD   12288   // (FDIM/32)*(DDIM/32) = 512*24
#define K1_CSR  (K1_UD + 1024)
#define K1_TOT  (K1_CSR + 1024)

__global__ __launch_bounds__(256) void k1_prep(const float* __restrict__ up_dec,
                                               const void* __restrict__ ii,
                                               const void* __restrict__ jj) {
    int b = blockIdx.x;
    if (b < K1_UD) {
        __shared__ float tile[32][33];
        int bx = b & 511;          // F tile
        int by = b >> 9;           // D tile
        int c0 = bx * 32, r0 = by * 32;
        int tx = threadIdx.x & 31, ty = threadIdx.x >> 5;   // (32, 8)
#pragma unroll
        for (int k = 0; k < 32; k += 8)
            tile[ty + k][tx] = __ldcs(&up_dec[(size_t)(r0 + ty + k) * FDIM + (c0 + tx)]);
        __syncthreads();
#pragma unroll
        for (int k = 0; k < 32; k += 8)
            g_udTh[(size_t)(c0 + ty + k) * DDIM + (r0 + tx)] = __float2half(tile[tx][ty + k]);
    } else if (b < K1_CSR) {
        int m = (b - K1_UD) * 256 + threadIdx.x;
        int is64 = detect_is64((const int*)ii);
        int cur = idx_at(ii, is64, m);
        int prev = (m == 0) ? -1 : idx_at(ii, is64, m - 1);
        for (int i = prev + 1; i <= cur; i++) g_rowstart[i] = m;
        if (m == MCONN - 1)
            for (int i = cur + 1; i <= FDIM; i++) g_rowstart[i] = MCONN;
    } else {
        int m = (b - K1_CSR) * 256 + threadIdx.x;
        int is64 = detect_is64((const int*)ii);
        g_j32[m] = idx_at(jj, is64, m);
    }
}

// ================================================================
// K2a: up_facts [NB,F] -> g_XTh [F,NB] fp16 (streaming reads)
// ================================================================
__global__ __launch_bounds__(256) void k2_xt(const float* __restrict__ up_facts) {
    __shared__ float tile[32][33];
    int bx = blockIdx.x & 511;     // F tile
    int by = blockIdx.x >> 9;      // NB tile
    int c0 = bx * 32, r0 = by * 32;
    int tx = threadIdx.x & 31, ty = threadIdx.x >> 5;
#pragma unroll
    for (int k = 0; k < 32; k += 8)
        tile[ty + k][tx] = __ldcs(&up_facts[(size_t)(r0 + ty + k) * FDIM + (c0 + tx)]);
    __syncthreads();
#pragma unroll
    for (int k = 0; k < 32; k += 8)
        g_XTh[(size_t)(c0 + ty + k) * NB + (r0 + tx)] = __float2half(tile[tx][ty + k]);
}

// ================================================================
// K2b: values[m] = <down_encoder[i_m,:], udT[j_m,:]> (fp16 gather,
// fp32 accumulate). One warp per i-group; de row in registers.
// ================================================================
__global__ __launch_bounds__(256) void k2_values(const float* __restrict__ de) {
    int warp = blockIdx.x * 8 + (threadIdx.x >> 5);
    int lane = threadIdx.x & 31;
    int i = warp;
    int s = g_rowstart[i];
    int e = g_rowstart[i + 1];
    if (s == e) return;

    // Cache de[i,:] lane slice: elements 8*(2*lane+64k) .. +7, k<3
    float a[3][8];
    const float4* dev = (const float4*)(de + (size_t)i * DDIM);
#pragma unroll
    for (int k = 0; k < 3; k++) {
        float4 p = dev[2 * lane + 64 * k];
        float4 q = dev[2 * lane + 64 * k + 1];
        a[k][0] = p.x; a[k][1] = p.y; a[k][2] = p.z; a[k][3] = p.w;
        a[k][4] = q.x; a[k][5] = q.y; a[k][6] = q.z; a[k][7] = q.w;
    }

    for (int m = s; m < e; m++) {
        int j = g_j32[m];
        const uint4* u = (const uint4*)(g_udTh + (size_t)j * DDIM);
        float sum = 0.f;
#pragma unroll
        for (int k = 0; k < 3; k++) {
            uint4 bb = u[lane + 32 * k];
            const __half2* h = (const __half2*)&bb;
#pragma unroll
            for (int t = 0; t < 4; t++) {
                float2 f = __half22float2(h[t]);
                sum += a[k][2 * t] * f.x + a[k][2 * t + 1] * f.y;
            }
        }
#pragma unroll
        for (int o = 16; o; o >>= 1) sum += __shfl_xor_sync(0xffffffffu, sum, o);
        if (lane == 0) g_values[m] = sum;
    }
}

// ================================================================
// K3: SpMM. out[n,i] = sum_{m in group(i)} values[m] * XT[j_m, n]
// Block: 256 threads, each thread owns 4 consecutive n (one 8B load
// per connection). Tile: ITILE=8 i-rows x all 1024 n. Grid 2048.
// smem entries pre-packed {byte_offset = j*NB*2, value}.
// ================================================================
#define ITILE 8
#define NTHR  256
#define CHUNK 512

__global__ __launch_bounds__(NTHR) void k3_spmm(float* __restrict__ out) {
    __shared__ int2 se[CHUNK];          // {xt byte offset, value bits}
    __shared__ int  soff[ITILE + 1];

    int i0 = blockIdx.x * ITILE;
    int n0 = threadIdx.x * 4;

    if (threadIdx.x <= ITILE) soff[threadIdx.x] = g_rowstart[i0 + threadIdx.x];
    __syncthreads();

    int mbase = soff[0];
    int mend  = soff[ITILE];

    const char* xbase = (const char*)g_XTh + n0 * 2;

    float4 acc[ITILE];
#pragma unroll
    for (int k = 0; k < ITILE; k++) acc[k] = make_float4(0.f, 0.f, 0.f, 0.f);

    for (int cb = mbase; cb < mend; cb += CHUNK) {
        int cend = min(cb + CHUNK, mend);
        __syncthreads();
        for (int t = cb + threadIdx.x; t < cend; t += NTHR) {
            int2 e;
            e.x = g_j32[t] << 11;            // j * NB * sizeof(half)
            e.y = __float_as_int(g_values[t]);
            se[t - cb] = e;
        }
        __syncthreads();
#pragma unroll
        for (int il = 0; il < ITILE; il++) {
            int ms = max(soff[il], cb);
            int me = min(soff[il + 1], cend);
            for (int m = ms; m < me; m++) {
                int2 e = se[m - cb];
                float v = __int_as_float(e.y);
                uint2 u = *(const uint2*)(xbase + e.x);
                float2 f0 = __half22float2(*(const __half2*)&u.x);
                float2 f1 = __half22float2(*(const __half2*)&u.y);
                acc[il].x += v * f0.x;
                acc[il].y += v * f0.y;
                acc[il].z += v * f1.x;
                acc[il].w += v * f1.y;
            }
        }
    }

    // Write 8 contiguous i-outputs (2 float4) for each of 4 n rows
#pragma unroll
    for (int r = 0; r < 4; r++) {
        float4* o = (float4*)(out + (size_t)(n0 + r) * FDIM + i0);
#pragma unroll
        for (int k = 0; k < 2; k++) {
            const float* s0 = (const float*)&acc[4 * k];
            const float* s1 = (const float*)&acc[4 * k + 1];
            const float* s2 = (const float*)&acc[4 * k + 2];
            const float* s3 = (const float*)&acc[4 * k + 3];
            o[k] = make_float4(s0[r], s1[r], s2[r], s3[r]);
        }
    }
}

// ---------------------------------------------------------------
extern "C" void kernel_launch(void* const* d_in, const int* in_sizes, int n_in,
                              void* d_out, int out_size) {
    const float* up_facts = (const float*)d_in[0];   // [NB, F]
    const float* down_enc = (const float*)d_in[1];   // [F, D]
    const float* up_dec   = (const float*)d_in[2];   // [D, F]
    const void*  ii       = d_in[3];                 // [M] sorted (int32 or int64)
    const void*  jj       = d_in[4];                 // [M]
    float* out = (float*)d_out;                      // [NB, F]

    k1_prep<<<K1_TOT, 256>>>(up_dec, ii, jj);
    k2_xt<<<16384, 256>>>(up_facts);              // (FDIM/32)*(NB/32)
    k2_values<<<FDIM / 8, 256>>>(down_enc);
    k3_spmm<<<FDIM / ITILE, NTHR>>>(out);
}